// round 5
// baseline (speedup 1.0000x reference)
#include <cuda_runtime.h>
#include <cuda_bf16.h>

// One warp per batch element. 8-qubit state (256 complex amps).
// Layout: lane bits 4..0 = qubits {0,1,2,4,6}; amp index bits 2..0 = {3,5,7}.
// The 8 amps/thread are packed into 4 f32x2 pairs along bit0 (q7):
// pack p holds amps (2p, 2p+1); pack bit1 = q3, pack bit0 = q5, half = q7.
// All gate arithmetic uses packed fma.rn.f32x2 (2 FMAs per fma-pipe slot).

#define NQ 8
#define FULLMASK 0xffffffffu

typedef unsigned long long u64;

// ---------- packed f32x2 helpers ----------
__device__ __forceinline__ u64 pk2(float a, float b) {
    u64 r;
    asm("mov.b64 %0,{%1,%2};" : "=l"(r)
        : "r"(__float_as_uint(a)), "r"(__float_as_uint(b)));
    return r;
}
__device__ __forceinline__ float2 unpk(u64 v) {
    unsigned a, b;
    asm("mov.b64 {%0,%1},%2;" : "=r"(a), "=r"(b) : "l"(v));
    return make_float2(__uint_as_float(a), __uint_as_float(b));
}
__device__ __forceinline__ u64 dup2(float a) { return pk2(a, a); }
__device__ __forceinline__ u64 f2fma(u64 a, u64 b, u64 c) {
    u64 d; asm("fma.rn.f32x2 %0,%1,%2,%3;" : "=l"(d) : "l"(a), "l"(b), "l"(c)); return d;
}
__device__ __forceinline__ u64 f2mul(u64 a, u64 b) {
    u64 d; asm("mul.rn.f32x2 %0,%1,%2;" : "=l"(d) : "l"(a), "l"(b)); return d;
}
__device__ __forceinline__ u64 f2add(u64 a, u64 b) {
    u64 d; asm("add.rn.f32x2 %0,%1,%2;" : "=l"(d) : "l"(a), "l"(b)); return d;
}
__device__ __forceinline__ u64 swp2(u64 v) { float2 t = unpk(v); return pk2(t.y, t.x); }
__device__ __forceinline__ u64 shfl2(u64 v, unsigned m) {
    float2 t = unpk(v);
    return pk2(__shfl_xor_sync(FULLMASK, t.x, m), __shfl_xor_sync(FULLMASK, t.y, m));
}

// ---------- packed coefficient storage ----------
// Per-branch block (u64 offsets):
//  OFF_CR  + g*4 : CR gate g: {dup(c), dup(s), dup(-s), pk(-s,s)}
//  OFF_LM0      : lane-u3 for u3[0]: 2 rows x 6 packs
//  OFF_M3       : pack-pair matrices (bit2), 2 variants x 12  (u3[1], R7*u3[1])
//  OFF_U2       : pack-pair matrix u3[2], 12
//  OFF_U4       : pack-pair matrix u3[4], 12
//  OFF_M7       : within-pack matrices, 2 variants x 6  (u5*u3, u5*R8*u3)
#define OFF_CR   0
#define OFF_LM0  40
#define OFF_M3   52
#define OFF_U2   76
#define OFF_U4   88
#define OFF_M7   100
#define BR_U64   112

__device__ u64 g_pk[3 * BR_U64];
__device__ u64 g_zx[256], g_zy[256], g_zyn[256];   // [layer*128 + pack*32 + lane]

// ---------- prep helpers ----------
__device__ void cmm(const float* A, const float* Bm, float* C) {
#pragma unroll
    for (int i = 0; i < 2; i++)
#pragma unroll
        for (int j = 0; j < 2; j++) {
            float ar0 = A[i*4+0], ai0 = A[i*4+1], ar1 = A[i*4+2], ai1 = A[i*4+3];
            float br0 = Bm[j*2], bi0 = Bm[j*2+1], br1 = Bm[4+j*2], bi1 = Bm[4+j*2+1];
            C[i*4+j*2]   = ar0*br0 - ai0*bi0 + ar1*br1 - ai1*bi1;
            C[i*4+j*2+1] = ar0*bi0 + ai0*br0 + ar1*bi1 + ai1*br1;
        }
}
__device__ void build_rot(int br, float theta, float* R) {
    float c = cosf(0.5f * theta), s = sinf(0.5f * theta);
    if (br == 0)      { R[0]=c; R[1]=0;  R[2]=0;  R[3]=-s; R[4]=0; R[5]=-s; R[6]=c; R[7]=0; }
    else if (br == 1) { R[0]=c; R[1]=0;  R[2]=-s; R[3]=0;  R[4]=s; R[5]=0;  R[6]=c; R[7]=0; }
    else              { R[0]=c; R[1]=-s; R[2]=0;  R[3]=0;  R[4]=0; R[5]=0;  R[6]=c; R[7]=s; }
}
// pack-pair matrix: 12 packs (broadcast coefficients)
__device__ void wr_pp(u64* d, const float* g) {
    d[0]=dup2(g[0]); d[1]=dup2(g[1]);  d[2]=dup2(-g[1]);
    d[3]=dup2(g[2]); d[4]=dup2(g[3]);  d[5]=dup2(-g[3]);
    d[6]=dup2(g[4]); d[7]=dup2(g[5]);  d[8]=dup2(-g[5]);
    d[9]=dup2(g[6]); d[10]=dup2(g[7]); d[11]=dup2(-g[7]);
}
// within-pack matrix: 6 packs, P=(m00,m11), Q=(m01,m10)
__device__ void wr_ip(u64* d, const float* g) {
    d[0]=pk2(g[0],g[6]); d[1]=pk2(g[1],g[7]); d[2]=pk2(-g[1],-g[7]);
    d[3]=pk2(g[2],g[4]); d[4]=pk2(g[3],g[5]); d[5]=pk2(-g[3],-g[5]);
}
// lane-u3: row0 (bit=0): self=m00, partner=m01; row1 (bit=1): self=m11, partner=m10
__device__ void wr_lane(u64* d, const float* g) {
    d[0]=dup2(g[0]); d[1]=dup2(g[1]);  d[2]=dup2(-g[1]);
    d[3]=dup2(g[2]); d[4]=dup2(g[3]);  d[5]=dup2(-g[3]);
    d[6]=dup2(g[6]); d[7]=dup2(g[7]);  d[8]=dup2(-g[7]);
    d[9]=dup2(g[4]); d[10]=dup2(g[5]); d[11]=dup2(-g[5]);
}

__global__ void prep_gates(const float* __restrict__ crx, const float* __restrict__ u3x,
                           const float* __restrict__ cry, const float* __restrict__ u3y,
                           const float* __restrict__ crz, const float* __restrict__ u3z) {
    int t = threadIdx.x;
    if (t < 3) {
        int br = t;
        const float* crp = (br == 0) ? crx : (br == 1) ? cry : crz;
        const float* u3p = (br == 0) ? u3x : (br == 1) ? u3y : u3z;
        float u[6][8];
#pragma unroll
        for (int k = 0; k < 6; k++) {
            float th = u3p[3*k], ph = u3p[3*k+1], lm = u3p[3*k+2];
            float ct = cosf(0.5f*th), st = sinf(0.5f*th);
            float cp = cosf(ph), sp = sinf(ph);
            float cl = cosf(lm), sl = sinf(lm);
            u[k][0] = ct;       u[k][1] = 0.f;
            u[k][2] = -cl*st;   u[k][3] = -sl*st;
            u[k][4] = cp*st;    u[k][5] = sp*st;
            u[k][6] = (cp*cl - sp*sl)*ct;
            u[k][7] = (sp*cl + cp*sl)*ct;
        }
        u64* C = g_pk + br * BR_U64;
#pragma unroll
        for (int g = 0; g < 10; g++) {
            float c = cosf(0.5f * crp[g]), s = sinf(0.5f * crp[g]);
            C[OFF_CR + g*4 + 0] = dup2(c);
            C[OFF_CR + g*4 + 1] = dup2(s);
            C[OFF_CR + g*4 + 2] = dup2(-s);
            C[OFF_CR + g*4 + 3] = pk2(-s, s);
        }
        wr_lane(C + OFF_LM0, u[0]);
        float R7[8], R8[8], tmp[8], m[8];
        build_rot(br, crp[7], R7);
        build_rot(br, crp[8], R8);
        // m3: variant0 = u3[1]; variant1 = R7*u3[1]  (Z: both = u3[1], CR(1,3) in ztab)
        wr_pp(C + OFF_M3, u[1]);
        if (br < 2) { cmm(R7, u[1], m); wr_pp(C + OFF_M3 + 12, m); }
        else        { wr_pp(C + OFF_M3 + 12, u[1]); }
        wr_pp(C + OFF_U2, u[2]);
        wr_pp(C + OFF_U4, u[4]);
        // m7: variant0 = u3[5]*u3[3]; variant1 = u3[5]*R8*u3[3]
        cmm(u[5], u[3], m);  wr_ip(C + OFF_M7, m);
        cmm(R8, u[3], tmp);  cmm(u[5], tmp, m);  wr_ip(C + OFF_M7 + 6, m);
    }
    // CRZ phase tables: t = layer*128 + pack*32 + lane
    {
        int l = t >> 7, idx = t & 127, p = idx >> 5, lane = idx & 31;
        int q0 = (lane>>4)&1, q1 = (lane>>3)&1, q2 = (lane>>2)&1;
        int q4 = (lane>>1)&1, q6 = lane&1;
        float ph[2];
#pragma unroll
        for (int h = 0; h < 2; h++) {
            int q3 = (p>>1)&1, q5 = p&1, q7 = h;
            int qv[8] = {q0,q1,q2,q3,q4,q5,q6,q7};
            float pp = 0.f;
            if (l == 0) {
                const int c1[7] = {0,2,4,6,1,3,5};
                const int t1[7] = {1,3,5,7,2,4,6};
#pragma unroll
                for (int i = 0; i < 7; i++)
                    if (qv[c1[i]]) pp += qv[t1[i]] ? 0.5f*crz[i] : -0.5f*crz[i];
            } else {
                if (qv[1]) pp += qv[3] ? 0.5f*crz[7] : -0.5f*crz[7];
                if (qv[3]) pp += qv[5] ? 0.5f*crz[9] : -0.5f*crz[9];
            }
            ph[h] = pp;
        }
        g_zx[t]  = pk2(cosf(ph[0]),  cosf(ph[1]));
        g_zy[t]  = pk2(sinf(ph[0]),  sinf(ph[1]));
        g_zyn[t] = pk2(-sinf(ph[0]), -sinf(ph[1]));
    }
}

// ---------- packed gate primitives ----------
// lane-target CR. PMASK: participating packs (reg-resident control).
template <int BR, unsigned PMASK>
__device__ __forceinline__ void cr_lane_pk(u64 (&VR)[4], u64 (&VI)[4],
        const u64* __restrict__ cs4, int tbit, bool act, int lane) {
    const u64 c2 = cs4[0], s2 = cs4[1], s2n = cs4[2];
    const unsigned m = 1u << tbit;
    const u64 csY = ((lane >> tbit) & 1) ? s2 : s2n;
#pragma unroll
    for (int p = 0; p < 4; p++) {
        if (!((PMASK >> p) & 1)) continue;
        u64 PR = shfl2(VR[p], m), PI = shfl2(VI[p], m);
        u64 nR, nI;
        if (BR == 0) { nR = f2fma(s2, PI, f2mul(c2, VR[p])); nI = f2fma(s2n, PR, f2mul(c2, VI[p])); }
        else         { nR = f2fma(csY, PR, f2mul(c2, VR[p])); nI = f2fma(csY, PI, f2mul(c2, VI[p])); }
        if (act) { VR[p] = nR; VI[p] = nI; }
    }
}

// pack-pair CR (target q3 or q5)
template <int BR>
__device__ __forceinline__ void cr_pp(u64& AR, u64& AI, u64& BRv, u64& BI,
        const u64* __restrict__ cs4, bool act) {
    const u64 c2 = cs4[0], s2 = cs4[1], s2n = cs4[2];
    u64 nAR, nAI, nBR, nBI;
    if (BR == 0) {
        nAR = f2fma(s2, BI, f2mul(c2, AR));   nAI = f2fma(s2n, BRv, f2mul(c2, AI));
        nBR = f2fma(s2, AI, f2mul(c2, BRv));  nBI = f2fma(s2n, AR, f2mul(c2, BI));
    } else {
        nAR = f2fma(s2n, BRv, f2mul(c2, AR)); nAI = f2fma(s2n, BI, f2mul(c2, AI));
        nBR = f2fma(s2, AR, f2mul(c2, BRv));  nBI = f2fma(s2, AI, f2mul(c2, BI));
    }
    if (act) { AR = nAR; AI = nAI; BRv = nBR; BI = nBI; }
}

// within-pack CR (target q7)
template <int BR>
__device__ __forceinline__ void cr_ip(u64& VR, u64& VI,
        const u64* __restrict__ cs4, bool act) {
    const u64 c2 = cs4[0], s2 = cs4[1], s2n = cs4[2], smix = cs4[3];
    u64 HR = swp2(VR), HI = swp2(VI);
    u64 nR, nI;
    if (BR == 0) { nR = f2fma(s2, HI, f2mul(c2, VR)); nI = f2fma(s2n, HR, f2mul(c2, VI)); }
    else         { nR = f2fma(smix, HR, f2mul(c2, VR)); nI = f2fma(smix, HI, f2mul(c2, VI)); }
    if (act) { VR = nR; VI = nI; }
}

// pack-pair generic u3 (12-pack matrix)
__device__ __forceinline__ void pp_u3(u64& AR, u64& AI, u64& BRv, u64& BI,
        const u64* __restrict__ M) {
    u64 nAR = f2fma(M[0], AR, f2fma(M[2], AI, f2fma(M[3], BRv, f2mul(M[5], BI))));
    u64 nAI = f2fma(M[1], AR, f2fma(M[0], AI, f2fma(M[4], BRv, f2mul(M[3], BI))));
    u64 nBR = f2fma(M[6], AR, f2fma(M[8], AI, f2fma(M[9], BRv, f2mul(M[11], BI))));
    u64 nBI = f2fma(M[7], AR, f2fma(M[6], AI, f2fma(M[10], BRv, f2mul(M[9], BI))));
    AR = nAR; AI = nAI; BRv = nBR; BI = nBI;
}

// within-pack generic u3 (6-pack matrix)
__device__ __forceinline__ void ip_u3(u64& VR, u64& VI, const u64* __restrict__ M) {
    u64 HR = swp2(VR), HI = swp2(VI);
    u64 nR = f2fma(M[0], VR, f2fma(M[2], VI, f2fma(M[3], HR, f2mul(M[5], HI))));
    u64 nI = f2fma(M[1], VR, f2fma(M[0], VI, f2fma(M[4], HR, f2mul(M[3], HI))));
    VR = nR; VI = nI;
}

// lane-target u3 for one pack (row-selected 6-pack coefficients)
__device__ __forceinline__ void lane_u3_p(u64& VR, u64& VI,
        const u64* __restrict__ M, unsigned m) {
    u64 PR = shfl2(VR, m), PI = shfl2(VI, m);
    u64 nR = f2fma(M[0], VR, f2fma(M[2], VI, f2fma(M[3], PR, f2mul(M[5], PI))));
    u64 nI = f2fma(M[1], VR, f2fma(M[0], VI, f2fma(M[4], PR, f2mul(M[3], PI))));
    VR = nR; VI = nI;
}

// CRZ phase layer
__device__ __forceinline__ void ztab_pk(u64 (&VR)[4], u64 (&VI)[4],
        const u64* __restrict__ zx, const u64* __restrict__ zy,
        const u64* __restrict__ zyn, int base, int lane) {
#pragma unroll
    for (int p = 0; p < 4; p++) {
        int i = base + p*32 + lane;
        u64 x = zx[i], y = zy[i], yn = zyn[i];
        u64 nR = f2fma(yn, VI[p], f2mul(x, VR[p]));
        u64 nI = f2fma(y, VR[p], f2mul(x, VI[p]));
        VR[p] = nR; VI[p] = nI;
    }
}

template <int BR>
__device__ __forceinline__ void run_branch(const u64 (&IR)[4], int lane,
        const u64* __restrict__ C,
        const u64* __restrict__ zx, const u64* __restrict__ zy,
        const u64* __restrict__ zyn,
        float& e3o, float& e7o) {
    u64 VR[4], VI[4];
    const u64 Z0 = dup2(0.f);
#pragma unroll
    for (int p = 0; p < 4; p++) { VR[p] = IR[p]; VI[p] = Z0; }
    const bool b4 = (lane>>4)&1, b3 = (lane>>3)&1, b2 = (lane>>2)&1;
    const bool b1 = (lane>>1)&1, b0 = lane&1;

    if (BR < 2) {
        cr_lane_pk<BR, 0xF>(VR, VI, C+OFF_CR+0*4, 3, b4, lane);           // CR(0,1)
        cr_pp<BR>(VR[0],VI[0],VR[2],VI[2], C+OFF_CR+1*4, b2);             // CR(2,3)
        cr_pp<BR>(VR[1],VI[1],VR[3],VI[3], C+OFF_CR+1*4, b2);
        cr_pp<BR>(VR[0],VI[0],VR[1],VI[1], C+OFF_CR+2*4, b1);             // CR(4,5)
        cr_pp<BR>(VR[2],VI[2],VR[3],VI[3], C+OFF_CR+2*4, b1);
#pragma unroll
        for (int p = 0; p < 4; p++)
            cr_ip<BR>(VR[p], VI[p], C+OFF_CR+3*4, b0);                    // CR(6,7)
        cr_lane_pk<BR, 0xF>(VR, VI, C+OFF_CR+4*4, 2, b3, lane);           // CR(1,2)
        cr_lane_pk<BR, 0xC>(VR, VI, C+OFF_CR+5*4, 1, true, lane);         // CR(3,4) ctrl q3
        cr_lane_pk<BR, 0xA>(VR, VI, C+OFF_CR+6*4, 0, true, lane);         // CR(5,6) ctrl q5
    } else {
        ztab_pk(VR, VI, zx, zy, zyn, 0, lane);                            // 7 CRZ phases
    }

    // u3[0] on wire1 (lane bit3)
    {
        const u64* M = C + OFF_LM0 + (b3 ? 6 : 0);
#pragma unroll
        for (int p = 0; p < 4; p++) lane_u3_p(VR[p], VI[p], M, 8);
    }
    // m3 (bit2): fused [u3[1]; CR(1,3)], variant by q1 (lane bit3)
    {
        const u64* M = C + OFF_M3 + (b3 ? 12 : 0);
        pp_u3(VR[0], VI[0], VR[2], VI[2], M);
        pp_u3(VR[1], VI[1], VR[3], VI[3], M);
    }
    // u3[2] (bit1)
    pp_u3(VR[0], VI[0], VR[1], VI[1], C + OFF_U2);
    pp_u3(VR[2], VI[2], VR[3], VI[3], C + OFF_U2);
    // m7 (within-pack): fused [u3[3]; CR(5,7); u3[5]], variant by q5 (pack bit0)
    ip_u3(VR[0], VI[0], C + OFF_M7);
    ip_u3(VR[1], VI[1], C + OFF_M7 + 6);
    ip_u3(VR[2], VI[2], C + OFF_M7);
    ip_u3(VR[3], VI[3], C + OFF_M7 + 6);

    if (BR < 2) {
        cr_pp<BR>(VR[2], VI[2], VR[3], VI[3], C+OFF_CR+9*4, true);        // CR(3,5)
    } else {
        ztab_pk(VR, VI, zx, zy, zyn, 128, lane);                          // (1,3)+(3,5)
    }
    // u3[4] (bit2)
    pp_u3(VR[0], VI[0], VR[2], VI[2], C + OFF_U4);
    pp_u3(VR[1], VI[1], VR[3], VI[3], C + OFF_U4);

    // expval_z: q3 = pack bit1, q7 = half
    u64 P0 = f2fma(VR[0], VR[0], f2mul(VI[0], VI[0]));
    u64 P1 = f2fma(VR[1], VR[1], f2mul(VI[1], VI[1]));
    u64 P2 = f2fma(VR[2], VR[2], f2mul(VI[2], VI[2]));
    u64 P3 = f2fma(VR[3], VR[3], f2mul(VI[3], VI[3]));
    u64 T01 = f2add(P0, P1), T23 = f2add(P2, P3);
    u64 E3 = f2fma(dup2(-1.f), T23, T01);
    u64 S  = f2add(T01, T23);
    float2 e3p = unpk(E3), sp = unpk(S);
    float e3 = e3p.x + e3p.y;
    float e7 = sp.x - sp.y;
#pragma unroll
    for (int o = 16; o; o >>= 1) {
        e3 += __shfl_xor_sync(FULLMASK, e3, o);
        e7 += __shfl_xor_sync(FULLMASK, e7, o);
    }
    e3o = e3; e7o = e7;
}

__global__ __launch_bounds__(256) void qcnn_main(
    const float* __restrict__ x,
    const float* __restrict__ w1, const float* __restrict__ b1,
    const float* __restrict__ w2, const float* __restrict__ b2,
    float* __restrict__ out, int B) {
    __shared__ u64  s_pk[3 * BR_U64];
    __shared__ u64  s_zx[256], s_zy[256], s_zyn[256];
    __shared__ float sw1[72], sb1[12], sw2[12], sb2s[1];

    int t = threadIdx.x;
    for (int i = t; i < 3 * BR_U64; i += 256) s_pk[i] = g_pk[i];
    s_zx[t] = g_zx[t]; s_zy[t] = g_zy[t]; s_zyn[t] = g_zyn[t];
    if (t < 72) sw1[t] = w1[t];
    if (t < 12) { sb1[t] = b1[t]; sw2[t] = w2[t]; }
    if (t == 0) sb2s[0] = b2[0];
    __syncthreads();

    int warp = (blockIdx.x * blockDim.x + t) >> 5;
    if (warp >= B) return;
    int lane = t & 31;

    // ---- encode ----
    float xv = x[(warp << 3) + (lane & 7)];
    float ch = __cosf(0.5f * xv);
    float sh = __sinf(0.5f * xv);
    float c0 = __shfl_sync(FULLMASK, ch, 0), s0 = __shfl_sync(FULLMASK, sh, 0);
    float c1 = __shfl_sync(FULLMASK, ch, 1), s1 = __shfl_sync(FULLMASK, sh, 1);
    float c2 = __shfl_sync(FULLMASK, ch, 2), s2 = __shfl_sync(FULLMASK, sh, 2);
    float c3 = __shfl_sync(FULLMASK, ch, 3), s3 = __shfl_sync(FULLMASK, sh, 3);
    float c4 = __shfl_sync(FULLMASK, ch, 4), s4 = __shfl_sync(FULLMASK, sh, 4);
    float c5 = __shfl_sync(FULLMASK, ch, 5), s5 = __shfl_sync(FULLMASK, sh, 5);
    float c6 = __shfl_sync(FULLMASK, ch, 6), s6 = __shfl_sync(FULLMASK, sh, 6);
    float c7 = __shfl_sync(FULLMASK, ch, 7), s7 = __shfl_sync(FULLMASK, sh, 7);

    // lane bits 4..0 = q0,q1,q2,q4,q6 ; pack bit1 = q3, bit0 = q5, half = q7
    float L = (((lane >> 4) & 1) ? s0 : c0)
            * (((lane >> 3) & 1) ? s1 : c1)
            * (((lane >> 2) & 1) ? s2 : c2)
            * (((lane >> 1) & 1) ? s4 : c4)
            * ((lane & 1) ? s6 : c6);

    u64 IR[4];
    u64 c7s7 = pk2(c7, s7);
#pragma unroll
    for (int p = 0; p < 4; p++) {
        float bb = L * ((p & 2) ? s3 : c3) * ((p & 1) ? s5 : c5);
        IR[p] = f2mul(dup2(bb), c7s7);
    }

    float f0, f1, f2, f3, f4, f5v;
    run_branch<0>(IR, lane, s_pk + 0*BR_U64, s_zx, s_zy, s_zyn, f0, f1);
    run_branch<1>(IR, lane, s_pk + 1*BR_U64, s_zx, s_zy, s_zyn, f2, f3);
    run_branch<2>(IR, lane, s_pk + 2*BR_U64, s_zx, s_zy, s_zyn, f4, f5v);

    // ---- MLP head: parallel over lanes 0..11 ----
    float contrib = 0.f;
    if (lane < 12) {
        float h = sb1[lane];
        h = fmaf(sw1[lane * 6 + 0], f0, h);
        h = fmaf(sw1[lane * 6 + 1], f1, h);
        h = fmaf(sw1[lane * 6 + 2], f2, h);
        h = fmaf(sw1[lane * 6 + 3], f3, h);
        h = fmaf(sw1[lane * 6 + 4], f4, h);
        h = fmaf(sw1[lane * 6 + 5], f5v, h);
        contrib = sw2[lane] * tanhf(h);
    }
#pragma unroll
    for (int o = 16; o; o >>= 1) contrib += __shfl_xor_sync(FULLMASK, contrib, o);
    if (lane == 0) out[warp] = 1.0f / (1.0f + expf(-(contrib + sb2s[0])));
}

extern "C" void kernel_launch(void* const* d_in, const int* in_sizes, int n_in,
                              void* d_out, int out_size) {
    const float* x    = (const float*)d_in[0];
    const float* crx  = (const float*)d_in[1];
    const float* u3x  = (const float*)d_in[2];
    const float* cry  = (const float*)d_in[3];
    const float* u3y  = (const float*)d_in[4];
    const float* crz  = (const float*)d_in[5];
    const float* u3z  = (const float*)d_in[6];
    const float* w1   = (const float*)d_in[7];
    const float* b1   = (const float*)d_in[8];
    const float* w2   = (const float*)d_in[9];
    const float* b2   = (const float*)d_in[10];
    float* out = (float*)d_out;

    int B = in_sizes[0] / NQ;   // 32768

    prep_gates<<<1, 256>>>(crx, u3x, cry, u3y, crz, u3z);

    int threads = 256;
    int blocks = (B + (threads / 32) - 1) / (threads / 32);
    qcnn_main<<<blocks, threads>>>(x, w1, b1, w2, b2, out, B);
}

// round 10
// speedup vs baseline: 1.5444x; 1.5444x over previous
#include <cuda_runtime.h>
#include <cuda_bf16.h>

// Two batch elements per warp, packed into f32x2 (pack = (elem0, elem1)).
// 8-qubit state (256 complex amps per element). Layout identical to R4:
// lane bits 4..0 = qubits {0,1,2,4,6}; reg r bits 2..0 = qubits {3,5,7}.
// Every gate op is elementwise on the pack -> fma.rn.f32x2 (FFMA2) serves
// both elements in one fma-pipe slot. No within-pack ops ever.

#define NQ 8
#define FULLMASK 0xffffffffu

typedef unsigned long long u64;

// ---------- packed helpers ----------
__device__ __forceinline__ u64 pk2(float a, float b) {
    u64 r;
    asm("mov.b64 %0,{%1,%2};" : "=l"(r)
        : "r"(__float_as_uint(a)), "r"(__float_as_uint(b)));
    return r;
}
__device__ __forceinline__ float2 unpk(u64 v) {
    unsigned a, b;
    asm("mov.b64 {%0,%1},%2;" : "=r"(a), "=r"(b) : "l"(v));
    return make_float2(__uint_as_float(a), __uint_as_float(b));
}
__device__ __forceinline__ u64 dup2(float a) { return pk2(a, a); }
__device__ __forceinline__ u64 f2fma(u64 a, u64 b, u64 c) {
    u64 d; asm("fma.rn.f32x2 %0,%1,%2,%3;" : "=l"(d) : "l"(a), "l"(b), "l"(c)); return d;
}
__device__ __forceinline__ u64 f2mul(u64 a, u64 b) {
    u64 d; asm("mul.rn.f32x2 %0,%1,%2;" : "=l"(d) : "l"(a), "l"(b)); return d;
}
__device__ __forceinline__ u64 f2add(u64 a, u64 b) {
    u64 d; asm("add.rn.f32x2 %0,%1,%2;" : "=l"(d) : "l"(a), "l"(b)); return d;
}
__device__ __forceinline__ u64 shfl2(u64 v, unsigned m) {
    return __shfl_xor_sync(FULLMASK, v, m);
}

// ---------- coefficient block layout (u64 offsets, per branch) ----------
#define OFF_CR   0     // 10 gates x {dup(c), dup(s), dup(-s)}
#define OFF_LM0  30    // lane-u3 u3[0]: 2 rows x 6
#define OFF_M3   42    // pack-pair matrices wire3: 2 variants x 12
#define OFF_U2   66    // u3[2]: 12
#define OFF_U4   78    // u3[4]: 12
#define OFF_M7   90    // fused wire7: 2 variants x 12
#define BR_U64   114

__device__ u64 g_pk[3 * BR_U64];
__device__ u64 g_zx[512], g_zy[512], g_zyn[512];  // [layer*256 + r*32 + lane]

// ---------- prep ----------
__device__ void cmm(const float* A, const float* Bm, float* C) {
#pragma unroll
    for (int i = 0; i < 2; i++)
#pragma unroll
        for (int j = 0; j < 2; j++) {
            float ar0 = A[i*4+0], ai0 = A[i*4+1], ar1 = A[i*4+2], ai1 = A[i*4+3];
            float br0 = Bm[j*2], bi0 = Bm[j*2+1], br1 = Bm[4+j*2], bi1 = Bm[4+j*2+1];
            C[i*4+j*2]   = ar0*br0 - ai0*bi0 + ar1*br1 - ai1*bi1;
            C[i*4+j*2+1] = ar0*bi0 + ai0*br0 + ar1*bi1 + ai1*br1;
        }
}
__device__ void build_rot(int br, float theta, float* R) {
    float c = cosf(0.5f * theta), s = sinf(0.5f * theta);
    if (br == 0)      { R[0]=c; R[1]=0;  R[2]=0;  R[3]=-s; R[4]=0; R[5]=-s; R[6]=c; R[7]=0; }
    else if (br == 1) { R[0]=c; R[1]=0;  R[2]=-s; R[3]=0;  R[4]=s; R[5]=0;  R[6]=c; R[7]=0; }
    else              { R[0]=c; R[1]=-s; R[2]=0;  R[3]=0;  R[4]=0; R[5]=0;  R[6]=c; R[7]=s; }
}
__device__ void wr_pp12(u64* d, const float* g) {
    d[0]=dup2(g[0]); d[1]=dup2(g[1]);  d[2]=dup2(-g[1]);
    d[3]=dup2(g[2]); d[4]=dup2(g[3]);  d[5]=dup2(-g[3]);
    d[6]=dup2(g[4]); d[7]=dup2(g[5]);  d[8]=dup2(-g[5]);
    d[9]=dup2(g[6]); d[10]=dup2(g[7]); d[11]=dup2(-g[7]);
}
__device__ void wr_lane12(u64* d, const float* g) {
    d[0]=dup2(g[0]); d[1]=dup2(g[1]);  d[2]=dup2(-g[1]);
    d[3]=dup2(g[2]); d[4]=dup2(g[3]);  d[5]=dup2(-g[3]);
    d[6]=dup2(g[6]); d[7]=dup2(g[7]);  d[8]=dup2(-g[7]);
    d[9]=dup2(g[4]); d[10]=dup2(g[5]); d[11]=dup2(-g[5]);
}

__global__ void prep_gates(const float* __restrict__ crx, const float* __restrict__ u3x,
                           const float* __restrict__ cry, const float* __restrict__ u3y,
                           const float* __restrict__ crz, const float* __restrict__ u3z) {
    int t = threadIdx.x;
    if (t < 3) {
        int br = t;
        const float* crp = (br == 0) ? crx : (br == 1) ? cry : crz;
        const float* u3p = (br == 0) ? u3x : (br == 1) ? u3y : u3z;
        float u[6][8];
#pragma unroll
        for (int k = 0; k < 6; k++) {
            float th = u3p[3*k], ph = u3p[3*k+1], lm = u3p[3*k+2];
            float ct = cosf(0.5f*th), st = sinf(0.5f*th);
            float cp = cosf(ph), sp = sinf(ph);
            float cl = cosf(lm), sl = sinf(lm);
            u[k][0] = ct;       u[k][1] = 0.f;
            u[k][2] = -cl*st;   u[k][3] = -sl*st;
            u[k][4] = cp*st;    u[k][5] = sp*st;
            u[k][6] = (cp*cl - sp*sl)*ct;
            u[k][7] = (sp*cl + cp*sl)*ct;
        }
        u64* C = g_pk + br * BR_U64;
#pragma unroll
        for (int g = 0; g < 10; g++) {
            float c = cosf(0.5f * crp[g]), s = sinf(0.5f * crp[g]);
            C[OFF_CR + g*3 + 0] = dup2(c);
            C[OFF_CR + g*3 + 1] = dup2(s);
            C[OFF_CR + g*3 + 2] = dup2(-s);
        }
        wr_lane12(C + OFF_LM0, u[0]);
        float R7[8], R8[8], tmp[8], m[8];
        build_rot(br, crp[7], R7);
        build_rot(br, crp[8], R8);
        wr_pp12(C + OFF_M3, u[1]);
        if (br < 2) { cmm(R7, u[1], m); wr_pp12(C + OFF_M3 + 12, m); }
        else        { wr_pp12(C + OFF_M3 + 12, u[1]); }
        wr_pp12(C + OFF_U2, u[2]);
        wr_pp12(C + OFF_U4, u[4]);
        cmm(u[5], u[3], m);  wr_pp12(C + OFF_M7, m);
        cmm(R8, u[3], tmp);  cmm(u[5], tmp, m);  wr_pp12(C + OFF_M7 + 12, m);
    }
    // CRZ phase tables: both layers for amp index t (r = t>>5, lane = t&31)
    {
        int lane = t & 31, r = t >> 5;
        int q0 = (lane>>4)&1, q1 = (lane>>3)&1, q2 = (lane>>2)&1;
        int q4 = (lane>>1)&1, q6 = lane&1;
        int q3 = (r>>2)&1, q5 = (r>>1)&1, q7 = r&1;
        int qv[8] = {q0,q1,q2,q3,q4,q5,q6,q7};
        const int c1[7] = {0,2,4,6,1,3,5};
        const int t1[7] = {1,3,5,7,2,4,6};
        float p1 = 0.f;
#pragma unroll
        for (int i = 0; i < 7; i++)
            if (qv[c1[i]]) p1 += qv[t1[i]] ? 0.5f*crz[i] : -0.5f*crz[i];
        float p2 = 0.f;
        if (qv[1]) p2 += qv[3] ? 0.5f*crz[7] : -0.5f*crz[7];
        if (qv[3]) p2 += qv[5] ? 0.5f*crz[9] : -0.5f*crz[9];
        g_zx[t]        = dup2(cosf(p1));
        g_zy[t]        = dup2(sinf(p1));
        g_zyn[t]       = dup2(-sinf(p1));
        g_zx[256 + t]  = dup2(cosf(p2));
        g_zy[256 + t]  = dup2(sinf(p2));
        g_zyn[256 + t] = dup2(-sinf(p2));
    }
}

// ---------- packed gates (structure identical to R4 scalar gates) ----------
template <int BR, unsigned RMASK>
__device__ __forceinline__ void cr_lane(u64 (&VR)[8], u64 (&VI)[8],
        const u64* __restrict__ cs, int tbit, bool act, int lane) {
    const u64 c2 = cs[0], s2 = cs[1], s2n = cs[2];
    const unsigned m = 1u << tbit;
    const u64 csY = ((lane >> tbit) & 1) ? s2 : s2n;
#pragma unroll
    for (int r = 0; r < 8; r++) {
        if (!((RMASK >> r) & 1)) continue;
        u64 PR = shfl2(VR[r], m), PI = shfl2(VI[r], m);
        u64 nR, nI;
        if (BR == 0) { nR = f2fma(s2,  PI, f2mul(c2, VR[r])); nI = f2fma(s2n, PR, f2mul(c2, VI[r])); }
        else         { nR = f2fma(csY, PR, f2mul(c2, VR[r])); nI = f2fma(csY, PI, f2mul(c2, VI[r])); }
        if (act) { VR[r] = nR; VI[r] = nI; }
    }
}

template <int BR, int TB, unsigned MASK>
__device__ __forceinline__ void cr_reg(u64 (&VR)[8], u64 (&VI)[8],
        const u64* __restrict__ cs, bool act) {
    const u64 c2 = cs[0], s2 = cs[1], s2n = cs[2];
#pragma unroll
    for (int r0 = 0; r0 < 8; r0++) {
        if (r0 & (1 << TB)) continue;
        if (!((MASK >> r0) & 1)) continue;
        const int r1 = r0 | (1 << TB);
        u64 AR = VR[r0], AI = VI[r0], BRv = VR[r1], BI = VI[r1];
        u64 n0R, n0I, n1R, n1I;
        if (BR == 0) {
            n0R = f2fma(s2,  BI,  f2mul(c2, AR));  n0I = f2fma(s2n, BRv, f2mul(c2, AI));
            n1R = f2fma(s2,  AI,  f2mul(c2, BRv)); n1I = f2fma(s2n, AR,  f2mul(c2, BI));
        } else {
            n0R = f2fma(s2n, BRv, f2mul(c2, AR));  n0I = f2fma(s2n, BI,  f2mul(c2, AI));
            n1R = f2fma(s2,  AR,  f2mul(c2, BRv)); n1I = f2fma(s2,  AI,  f2mul(c2, BI));
        }
        if (act) { VR[r0] = n0R; VI[r0] = n0I; VR[r1] = n1R; VI[r1] = n1I; }
    }
}

__device__ __forceinline__ void ztab(u64 (&VR)[8], u64 (&VI)[8],
        const u64* __restrict__ zx, const u64* __restrict__ zy,
        const u64* __restrict__ zyn, int base, int lane) {
#pragma unroll
    for (int r = 0; r < 8; r++) {
        int i = base + r*32 + lane;
        u64 x = zx[i], y = zy[i], yn = zyn[i];
        u64 nR = f2fma(yn, VI[r], f2mul(x, VR[r]));
        u64 nI = f2fma(y,  VR[r], f2mul(x, VI[r]));
        VR[r] = nR; VI[r] = nI;
    }
}

__device__ __forceinline__ void u3_lane(u64 (&VR)[8], u64 (&VI)[8],
        const u64* __restrict__ Mbase, int tbit, int lane) {
    const u64* M = Mbase + (((lane >> tbit) & 1) ? 6 : 0);
    const u64 M0 = M[0], M1 = M[1], M2 = M[2], M3 = M[3], M4 = M[4], M5 = M[5];
    const unsigned m = 1u << tbit;
#pragma unroll
    for (int r = 0; r < 8; r++) {
        u64 PR = shfl2(VR[r], m), PI = shfl2(VI[r], m);
        u64 nR = f2fma(M0, VR[r], f2fma(M2, VI[r], f2fma(M3, PR, f2mul(M5, PI))));
        u64 nI = f2fma(M1, VR[r], f2fma(M0, VI[r], f2fma(M4, PR, f2mul(M3, PI))));
        VR[r] = nR; VI[r] = nI;
    }
}

__device__ __forceinline__ void pp_u3(u64& AR, u64& AI, u64& BRv, u64& BI,
        const u64* __restrict__ M) {
    u64 nAR = f2fma(M[0], AR, f2fma(M[2],  AI, f2fma(M[3], BRv, f2mul(M[5],  BI))));
    u64 nAI = f2fma(M[1], AR, f2fma(M[0],  AI, f2fma(M[4], BRv, f2mul(M[3],  BI))));
    u64 nBR = f2fma(M[6], AR, f2fma(M[8],  AI, f2fma(M[9], BRv, f2mul(M[11], BI))));
    u64 nBI = f2fma(M[7], AR, f2fma(M[6],  AI, f2fma(M[10],BRv, f2mul(M[9],  BI))));
    AR = nAR; AI = nAI; BRv = nBR; BI = nBI;
}

template <int TB, unsigned MASK>
__device__ __forceinline__ void u3_reg(u64 (&VR)[8], u64 (&VI)[8],
        const u64* __restrict__ M) {
#pragma unroll
    for (int r0 = 0; r0 < 8; r0++) {
        if (r0 & (1 << TB)) continue;
        if (!((MASK >> r0) & 1)) continue;
        const int r1 = r0 | (1 << TB);
        pp_u3(VR[r0], VI[r0], VR[r1], VI[r1], M);
    }
}

template <int TB, unsigned MASK, int SELBIT>
__device__ __forceinline__ void u3_reg2(u64 (&VR)[8], u64 (&VI)[8],
        const u64* __restrict__ ga, const u64* __restrict__ gb) {
#pragma unroll
    for (int r0 = 0; r0 < 8; r0++) {
        if (r0 & (1 << TB)) continue;
        if (!((MASK >> r0) & 1)) continue;
        const u64* M = ((r0 >> SELBIT) & 1) ? gb : ga;
        const int r1 = r0 | (1 << TB);
        pp_u3(VR[r0], VI[r0], VR[r1], VI[r1], M);
    }
}

template <int BR>
__device__ __forceinline__ void run_branch(const u64 (&IR)[8], int lane,
        const u64* __restrict__ C,
        const u64* __restrict__ zx, const u64* __restrict__ zy,
        const u64* __restrict__ zyn,
        u64& e3o, u64& e7o) {
    u64 VR[8], VI[8];
    const u64 Z0 = dup2(0.f);
#pragma unroll
    for (int r = 0; r < 8; r++) { VR[r] = IR[r]; VI[r] = Z0; }
    const bool b4 = (lane>>4)&1, b3 = (lane>>3)&1, b2 = (lane>>2)&1;
    const bool b1 = (lane>>1)&1, b0 = lane&1;

    if (BR < 2) {
        cr_lane<BR, 0xFF>(VR, VI, C+OFF_CR+0*3, 3, b4, lane);   // CR(0,1)
        cr_reg<BR, 2, 0x0F>(VR, VI, C+OFF_CR+1*3, b2);          // CR(2,3)
        cr_reg<BR, 1, 0x33>(VR, VI, C+OFF_CR+2*3, b1);          // CR(4,5)
        cr_reg<BR, 0, 0x55>(VR, VI, C+OFF_CR+3*3, b0);          // CR(6,7)
        cr_lane<BR, 0xFF>(VR, VI, C+OFF_CR+4*3, 2, b3, lane);   // CR(1,2)
        cr_lane<BR, 0xF0>(VR, VI, C+OFF_CR+5*3, 1, true, lane); // CR(3,4) ctrl q3
        cr_lane<BR, 0xCC>(VR, VI, C+OFF_CR+6*3, 0, true, lane); // CR(5,6) ctrl q5
    } else {
        ztab(VR, VI, zx, zy, zyn, 0, lane);                     // 7 CRZ phases
    }

    u3_lane(VR, VI, C + OFF_LM0, 3, lane);                      // u3[0] wire1
    {
        const u64* M = C + OFF_M3 + (b3 ? 12 : 0);              // fused [u3[1]; CR(1,3)]
        u3_reg<2, 0x0F>(VR, VI, M);
    }
    u3_reg<1, 0x33>(VR, VI, C + OFF_U2);                        // u3[2] wire5
    u3_reg2<0, 0x55, 1>(VR, VI, C + OFF_M7, C + OFF_M7 + 12);   // fused wire7

    if (BR < 2) {
        // CR(3,5): ctrl q3 = reg bit2 set, target q5 = reg bit1.
        // Active low pairs r0 = {4,5}  (FIX: was 0x50 in R6, dropping pair (5,7))
        cr_reg<BR, 1, 0x30>(VR, VI, C+OFF_CR+9*3, true);
    } else {
        ztab(VR, VI, zx, zy, zyn, 256, lane);                   // (1,3)+(3,5)
    }
    u3_reg<2, 0x0F>(VR, VI, C + OFF_U4);                        // u3[4] wire3

    // expval_z: q3 = reg bit2 (sign - for r&4), q7 = reg bit0 (- for r&1)
    u64 P[8];
#pragma unroll
    for (int r = 0; r < 8; r++) P[r] = f2fma(VR[r], VR[r], f2mul(VI[r], VI[r]));
    const u64 NEG1 = dup2(-1.f);
    u64 A3 = f2add(f2add(P[0], P[1]), f2add(P[2], P[3]));
    u64 B3 = f2add(f2add(P[4], P[5]), f2add(P[6], P[7]));
    u64 E3 = f2fma(NEG1, B3, A3);
    u64 A7 = f2add(f2add(P[0], P[2]), f2add(P[4], P[6]));
    u64 B7 = f2add(f2add(P[1], P[3]), f2add(P[5], P[7]));
    u64 E7 = f2fma(NEG1, B7, A7);
#pragma unroll
    for (int o = 16; o; o >>= 1) {
        E3 = f2add(E3, shfl2(E3, o));
        E7 = f2add(E7, shfl2(E7, o));
    }
    e3o = E3; e7o = E7;
}

__global__ __launch_bounds__(256, 3) void qcnn_main(
    const float* __restrict__ x,
    const float* __restrict__ w1, const float* __restrict__ b1,
    const float* __restrict__ w2, const float* __restrict__ b2,
    float* __restrict__ out, int npairs) {
    __shared__ u64 s_pk[3 * BR_U64];
    __shared__ u64 s_zx[512], s_zy[512], s_zyn[512];
    __shared__ float sw1[72], sb1[12], sw2[12], sb2s[1];

    int t = threadIdx.x;
    for (int i = t; i < 3 * BR_U64; i += 256) s_pk[i] = g_pk[i];
    for (int i = t; i < 512; i += 256) {
        s_zx[i] = g_zx[i]; s_zy[i] = g_zy[i]; s_zyn[i] = g_zyn[i];
    }
    if (t < 72) sw1[t] = w1[t];
    if (t < 12) { sb1[t] = b1[t]; sw2[t] = w2[t]; }
    if (t == 0) sb2s[0] = b2[0];
    __syncthreads();

    int wp = (blockIdx.x * blockDim.x + t) >> 5;   // batch pair index
    if (wp >= npairs) return;
    int lane = t & 31;

    // ---- encode both elements: lanes 0-7 hold elem0 angles, 8-15 elem1 ----
    float xv = (lane < 16) ? x[wp * 16 + lane] : 0.f;
    float ch = __cosf(0.5f * xv);
    float sh = __sinf(0.5f * xv);

    u64 IR[8];
    {
        float in[2][8];
#pragma unroll
        for (int e = 0; e < 2; e++) {
            float c0 = __shfl_sync(FULLMASK, ch, e*8+0), s0 = __shfl_sync(FULLMASK, sh, e*8+0);
            float c1 = __shfl_sync(FULLMASK, ch, e*8+1), s1 = __shfl_sync(FULLMASK, sh, e*8+1);
            float c2 = __shfl_sync(FULLMASK, ch, e*8+2), s2 = __shfl_sync(FULLMASK, sh, e*8+2);
            float c3 = __shfl_sync(FULLMASK, ch, e*8+3), s3 = __shfl_sync(FULLMASK, sh, e*8+3);
            float c4 = __shfl_sync(FULLMASK, ch, e*8+4), s4 = __shfl_sync(FULLMASK, sh, e*8+4);
            float c5 = __shfl_sync(FULLMASK, ch, e*8+5), s5 = __shfl_sync(FULLMASK, sh, e*8+5);
            float c6 = __shfl_sync(FULLMASK, ch, e*8+6), s6 = __shfl_sync(FULLMASK, sh, e*8+6);
            float c7 = __shfl_sync(FULLMASK, ch, e*8+7), s7 = __shfl_sync(FULLMASK, sh, e*8+7);
            // lane bits 4..0 = q0,q1,q2,q4,q6 ; reg bits 2..0 = q3,q5,q7
            float L = (((lane >> 4) & 1) ? s0 : c0)
                    * (((lane >> 3) & 1) ? s1 : c1)
                    * (((lane >> 2) & 1) ? s2 : c2)
                    * (((lane >> 1) & 1) ? s4 : c4)
                    * ((lane & 1) ? s6 : c6);
#pragma unroll
            for (int r = 0; r < 8; r++)
                in[e][r] = L * ((r & 4) ? s3 : c3) * ((r & 2) ? s5 : c5) * ((r & 1) ? s7 : c7);
        }
#pragma unroll
        for (int r = 0; r < 8; r++) IR[r] = pk2(in[0][r], in[1][r]);
    }

    u64 F[6];
    run_branch<0>(IR, lane, s_pk + 0*BR_U64, s_zx, s_zy, s_zyn, F[0], F[1]);
    run_branch<1>(IR, lane, s_pk + 1*BR_U64, s_zx, s_zy, s_zyn, F[2], F[3]);
    run_branch<2>(IR, lane, s_pk + 2*BR_U64, s_zx, s_zy, s_zyn, F[4], F[5]);

    // ---- MLP head: lanes 0-11 -> elem0, lanes 16-27 -> elem1 ----
    const int j = lane & 15;
    const int hi = lane >> 4;
    float f[6];
#pragma unroll
    for (int k = 0; k < 6; k++) {
        float2 v = unpk(F[k]);
        f[k] = hi ? v.y : v.x;
    }
    float contrib = 0.f;
    if (j < 12) {
        float h = sb1[j];
#pragma unroll
        for (int k = 0; k < 6; k++) h = fmaf(sw1[j * 6 + k], f[k], h);
        contrib = sw2[j] * tanhf(h);
    }
#pragma unroll
    for (int o = 8; o; o >>= 1) contrib += __shfl_xor_sync(FULLMASK, contrib, o);
    if (j == 0) out[wp * 2 + hi] = 1.0f / (1.0f + expf(-(contrib + sb2s[0])));
}

extern "C" void kernel_launch(void* const* d_in, const int* in_sizes, int n_in,
                              void* d_out, int out_size) {
    const float* x    = (const float*)d_in[0];
    const float* crx  = (const float*)d_in[1];
    const float* u3x  = (const float*)d_in[2];
    const float* cry  = (const float*)d_in[3];
    const float* u3y  = (const float*)d_in[4];
    const float* crz  = (const float*)d_in[5];
    const float* u3z  = (const float*)d_in[6];
    const float* w1   = (const float*)d_in[7];
    const float* b1   = (const float*)d_in[8];
    const float* w2   = (const float*)d_in[9];
    const float* b2   = (const float*)d_in[10];
    float* out = (float*)d_out;

    int B = in_sizes[0] / NQ;      // 32768
    int npairs = B / 2;            // 16384

    prep_gates<<<1, 256>>>(crx, u3x, cry, u3y, crz, u3z);

    int threads = 256;
    int blocks = (npairs + (threads / 32) - 1) / (threads / 32);
    qcnn_main<<<blocks, threads>>>(x, w1, b1, w2, b2, out, npairs);
}